// round 15
// baseline (speedup 1.0000x reference)
#include <cuda_runtime.h>
#include <cuda_fp16.h>
#include <cstdint>
#include <math.h>

#define E_ 8
#define D_ 2048
#define H_ 8192
#define R_ 64
#define N_ 4096
#define T64 144
#define T128 72
#define P_PAD (T128*128)

__device__ __align__(16) __half    g_xh [(size_t)N_*D_];
__device__ __align__(16) uint32_t  g_u1p[(size_t)E_*(D_/2)*R_];   // [E][D/2][R]
__device__ __align__(16) uint32_t  g_v1p[(size_t)E_*(R_/2)*H_];   // [E][R/2][H]
__device__ __align__(16) uint32_t  g_u2p[(size_t)E_*(H_/2)*R_];   // [E][H/2][R]
__device__ __align__(16) uint32_t  g_v2p[(size_t)E_*(R_/2)*D_];   // [E][R/2][D]
__device__ __align__(16) float     g_t1p[(size_t)4*P_PAD*R_];     // 4 K-quarter partials
__device__ __align__(16) float     g_t2 [(size_t)4*P_PAD*R_];
__device__ __align__(16) __half    g_py [(size_t)P_PAD*D_];
__device__ int   g_ptok[P_PAD];
__device__ float g_pw  [P_PAD];
__device__ int   g_entry[2*N_];
__device__ int   g_re[2*N_];
__device__ float g_rw[2*N_];
__device__ int   g_cnt[E_];                 // static-init 0; reset each run by k_sa
__device__ int   g_te64[T64];
__device__ int   g_te128[T128];

// ------------------------------- helpers ------------------------------------
#define GDC_WAIT()   asm volatile("griddepcontrol.wait;" ::: "memory")
#define GDC_LAUNCH() asm volatile("griddepcontrol.launch_dependents;")

__device__ __forceinline__ void mma16(float c[4], uint32_t a0, uint32_t a1,
                                      uint32_t a2, uint32_t a3,
                                      uint32_t b0, uint32_t b1) {
    asm volatile("mma.sync.aligned.m16n8k16.row.col.f32.f16.f16.f32 "
        "{%0,%1,%2,%3}, {%4,%5,%6,%7}, {%8,%9}, {%0,%1,%2,%3};"
        : "+f"(c[0]), "+f"(c[1]), "+f"(c[2]), "+f"(c[3])
        : "r"(a0), "r"(a1), "r"(a2), "r"(a3), "r"(b0), "r"(b1));
}
__device__ __forceinline__ void ldmA(uint32_t a[4], uint32_t addr) {
    asm volatile("ldmatrix.sync.aligned.m8n8.x4.shared.b16 {%0,%1,%2,%3}, [%4];"
        : "=r"(a[0]), "=r"(a[1]), "=r"(a[2]), "=r"(a[3]) : "r"(addr));
}
__device__ __forceinline__ uint32_t s2u(const void* p) {
    return (uint32_t)__cvta_generic_to_shared(p);
}
__device__ __forceinline__ void cpa(void* s, const void* g) {
    uint32_t sa=(uint32_t)__cvta_generic_to_shared(s);
    asm volatile("cp.async.cg.shared.global [%0], [%1], 16;" :: "r"(sa), "l"(g));
}
#define CPC  asm volatile("cp.async.commit_group;" ::: "memory")
#define CPW0 asm volatile("cp.async.wait_group 0;" ::: "memory")
#define CPW1 asm volatile("cp.async.wait_group 1;" ::: "memory")
#define CPW2 asm volatile("cp.async.wait_group 2;" ::: "memory")

// merged: blocks [0,512) = route + x->half ; blocks [512,1536) = weight packing
__global__ __launch_bounds__(256) void k_prert(
        const float* __restrict__ x, const float* __restrict__ gw,
        const float* __restrict__ gb,
        const float* __restrict__ u1, const float* __restrict__ v1,
        const float* __restrict__ u2, const float* __restrict__ v2) {
    if (blockIdx.x < 512) {
        int warp=threadIdx.x>>5, lane=threadIdx.x&31;
        int n = blockIdx.x*8 + warp;
        const float4* xr = (const float4*)(x + (size_t)n*D_);
        float4 xv[16];
#pragma unroll
        for (int i=0;i<16;i++) xv[i]=xr[lane+i*32];
#pragma unroll
        for (int i=0;i<16;i++){
            __half* dst = g_xh + (size_t)n*D_ + (size_t)(lane+i*32)*4;
            *(__half2*)dst     = __floats2half2_rn(xv[i].x, xv[i].y);
            *(__half2*)(dst+2) = __floats2half2_rn(xv[i].z, xv[i].w);
        }
        float lg[8];
#pragma unroll
        for (int e=0;e<8;e++){
            const float4* gr=(const float4*)(gw+(size_t)e*D_);
            float s=0.f;
#pragma unroll
            for (int i=0;i<16;i++){float4 g=gr[lane+i*32];
                s+=xv[i].x*g.x+xv[i].y*g.y+xv[i].z*g.z+xv[i].w*g.w;}
#pragma unroll
            for (int o=16;o>0;o>>=1) s+=__shfl_xor_sync(0xffffffffu,s,o);
            lg[e]=s+gb[e];
        }
        if (lane==0){
            int e0=0; float m0=lg[0];
#pragma unroll
            for (int e=1;e<8;e++) if (lg[e]>m0){m0=lg[e];e0=e;}
            int e1=-1; float m1=-3.4e38f;
#pragma unroll
            for (int e=0;e<8;e++) if (e!=e0 && lg[e]>m1){m1=lg[e];e1=e;}
            float w0=1.f/(1.f+expf(m1-m0));
            g_re[2*n]=e0; g_rw[2*n]=w0; g_re[2*n+1]=e1; g_rw[2*n+1]=1.f-w0;
            atomicAdd(&g_cnt[e0],1); atomicAdd(&g_cnt[e1],1);
        }
        return;
    }
    int tid = (blockIdx.x-512)*blockDim.x + threadIdx.x, st = 1024*blockDim.x;
    for (int i=tid;i<P_PAD;i+=st){ g_ptok[i]=0; g_pw[i]=0.f; }
    for (int i=tid;i<E_*(D_/2)*R_;i+=st){
        int e=i/((D_/2)*R_), rem=i%((D_/2)*R_), kk=rem/R_, r=rem%R_;
        const float* s=u1+(size_t)e*D_*R_+(size_t)(2*kk)*R_+r;
        ((__half2*)g_u1p)[i]=__floats2half2_rn(s[0], s[R_]);
    }
    for (int i=tid;i<E_*(R_/2)*H_;i+=st){
        int e=i/((R_/2)*H_), rem=i%((R_/2)*H_), kk=rem/H_, h=rem%H_;
        const float* s=v1+(size_t)e*R_*H_+(size_t)(2*kk)*H_+h;
        ((__half2*)g_v1p)[i]=__floats2half2_rn(s[0], s[H_]);
    }
    for (int i=tid;i<E_*(H_/2)*R_;i+=st){
        int e=i/((H_/2)*R_), rem=i%((H_/2)*R_), hh=rem/R_, r=rem%R_;
        const float* s=u2+(size_t)e*H_*R_+(size_t)(2*hh)*R_+r;
        ((__half2*)g_u2p)[i]=__floats2half2_rn(s[0], s[R_]);
    }
    for (int i=tid;i<E_*(R_/2)*D_;i+=st){
        int e=i/((R_/2)*D_), rem=i%((R_/2)*D_), kk=rem/D_, d=rem%D_;
        const float* s=v2+(size_t)e*R_*D_+(size_t)(2*kk)*D_+d;
        ((__half2*)g_v2p)[i]=__floats2half2_rn(s[0], s[D_]);
    }
}

// fused scan + assign : ONE block, 1024 threads, smem counters.
__global__ __launch_bounds__(1024) void k_sa() {
    GDC_WAIT();                       // prert outputs
    __shared__ int pre[E_+1];
    __shared__ int cur[E_];
    int tid=threadIdx.x, lane=tid&31;
    if (tid==0){
        int run=0;
        for (int e=0;e<E_;e++){ pre[e]=run; cur[e]=run;
            run += ((g_cnt[e]+127)>>7)<<7;
            g_cnt[e]=0; }
        pre[E_]=run;
    }
    __syncthreads();
    if (tid<T64){
        int r=tid*64, e=-1;
#pragma unroll
        for (int i=0;i<E_;i++) if (r>=pre[i] && r<pre[i+1]) e=i;
        g_te64[tid]=e;
    }
    if (tid<T128){
        int r=tid*128, e=-1;
#pragma unroll
        for (int i=0;i<E_;i++) if (r>=pre[i] && r<pre[i+1]) e=i;
        g_te128[tid]=e;
    }
    for (int n=tid;n<N_;n+=1024){
#pragma unroll
        for (int k=0;k<2;k++){
            int e=g_re[2*n+k];
            unsigned mask=__match_any_sync(0xffffffffu, e);
            int leader=__ffs(mask)-1;
            int rank=__popc(mask & ((1u<<lane)-1u));
            int base=0;
            if (lane==leader) base=atomicAdd(&cur[e], __popc(mask));
            base=__shfl_sync(0xffffffffu, base, leader);
            int pos=base+rank;
            g_ptok[pos]=n; g_pw[pos]=g_rw[2*n+k]; g_entry[2*n+k]=pos;
        }
    }
}

// ----- t1 partial = x @ u1 over one K-quarter (fp16, fp32 partial out) -------
#define T1_SMEM (256 + 2*64*72*2 + 2*32*72*4)
__global__ __launch_bounds__(256,3) void k_t1() {
    GDC_LAUNCH();                     // sa complete when we start -> mid may launch
    GDC_WAIT();                       // sa outputs
    int tile=blockIdx.x>>2, kq=blockIdx.x&3;
    int e=g_te64[tile]; if (e<0) return;
    int p0=tile*64, kbase=kq*(D_/4);
    extern __shared__ __align__(16) char smraw[];
    int*      tok=(int*)smraw;
    __half*   as=(__half*)(smraw+256);
    uint32_t* bs=(uint32_t*)(smraw+256+2*64*72*2);
    int tid=threadIdx.x, warp=tid>>5, lane=tid&31;
    int grp=lane>>2, tig=lane&3, wm=warp>>2, wn=warp&3;
    int lr=lane&15, lc=(lane>>4)*8;
    if (tid<64) tok[tid]=g_ptok[p0+tid];
    __syncthreads();
    const uint32_t* u1e = g_u1p + (size_t)e*(D_/2)*R_;
    const int NC=(D_/4)/64;
    uint32_t as_u = s2u(as);
    auto issue=[&](int c){
        int buf=c&1, k0=kbase+c*64;
        __half* ab=as+buf*64*72; uint32_t* bb=bs+buf*32*72;
#pragma unroll
        for (int j=0;j<2;j++){int idx=tid+j*256, row=idx>>3, q=idx&7;
            cpa(&ab[row*72+q*8], g_xh+(size_t)tok[row]*D_+k0+q*8);}
#pragma unroll
        for (int j=0;j<2;j++){int idx=tid+j*256, row=idx>>4, q=idx&15;
            cpa(&bb[row*72+q*4], u1e+(size_t)(k0/2+row)*R_+q*4);}
    };
    float acc[2][2][4];
#pragma unroll
    for (int a=0;a<2;a++)
#pragma unroll
        for (int b=0;b<2;b++)
#pragma unroll
            for (int q=0;q<4;q++) acc[a][b][q]=0.f;
    issue(0); CPC;
    for (int c=0;c<NC;c++){
        if (c>0) __syncthreads();
        if (c+1<NC){ issue(c+1); CPC; CPW1; } else { CPW0; }
        __syncthreads();
        int buf=c&1;
        uint32_t ab_u = as_u + (uint32_t)buf*64*72*2;
        const uint32_t* bb=bs+buf*32*72;
#pragma unroll
        for (int kk=0;kk<4;kk++){
            uint32_t fa[2][4];
#pragma unroll
            for (int mi=0;mi<2;mi++)
                ldmA(fa[mi], ab_u + (uint32_t)(((wm*32+mi*16+lr)*72 + kk*16 + lc)*2));
#pragma unroll
            for (int ni=0;ni<2;ni++){
                int n=wn*16+ni*8+grp;
                uint32_t b0=bb[(8*kk+tig)*72+n], b1=bb[(8*kk+tig+4)*72+n];
#pragma unroll
                for (int mi=0;mi<2;mi++)
                    mma16(acc[mi][ni],fa[mi][0],fa[mi][1],fa[mi][2],fa[mi][3],b0,b1);
            }
        }
    }
    float* dst = g_t1p + (size_t)kq*P_PAD*R_;
#pragma unroll
    for (int mi=0;mi<2;mi++)
#pragma unroll
        for (int ni=0;ni<2;ni++){
            int r0=wm*32+mi*16+grp, c0=wn*16+ni*8+2*tig;
            *(float2*)(dst+(size_t)(p0+r0)*R_+c0)   = make_float2(acc[mi][ni][0],acc[mi][ni][1]);
            *(float2*)(dst+(size_t)(p0+r0+8)*R_+c0) = make_float2(acc[mi][ni][2],acc[mi][ni][3]);
        }
}

// -------- mid: pipelined t2_q = relu(t1@v1+b1)@u2 over one H-quarter ---------
#define CH 32
#define NCM ((H_/4)/CH)
#define OFF_T1S 0
#define OFF_HS  (128*72*2)
#define OFF_W   (OFF_HS + 2*128*40*2)
#define WBUF    (32*40*4 + 16*72*4 + 32*4)
#define MID_SMEM (OFF_W + 4*WBUF)
__global__ __launch_bounds__(256,2) void k_mid(const float* __restrict__ b1) {
    GDC_LAUNCH();                     // t1 started after sa done -> y may launch
    int tile=blockIdx.x>>2, q=blockIdx.x&3;
    int e=g_te128[tile];              // sa output: complete (t1 started before us)
    if (e<0) { GDC_WAIT(); return; }
    int p0=tile*128, hbase=q*(H_/4);
    extern __shared__ __align__(16) char smraw[];
    __half* t1s=(__half*)(smraw+OFF_T1S);
    __half* hs =(__half*)(smraw+OFF_HS);
    char*   wb =(char*)(smraw+OFF_W);
    int tid=threadIdx.x, warp=tid>>5, lane=tid&31;
    int grp=lane>>2, tig=lane&3, wm=warp&3, wn=warp>>2;
    int lr=lane&15, lc=(lane>>4)*8;
    const uint32_t* v1e = g_v1p + (size_t)e*(R_/2)*H_;
    const uint32_t* u2e = g_u2p + (size_t)e*(H_/2)*R_;
    const float*    b1e = b1 + (size_t)e*H_;
    auto VB=[&](int buf)->uint32_t* { return (uint32_t*)(wb + buf*WBUF); };
    auto UB=[&](int buf)->uint32_t* { return (uint32_t*)(wb + buf*WBUF + 32*40*4); };
    auto BB=[&](int buf)->float*    { return (float*)(wb + buf*WBUF + 32*40*4 + 16*72*4); };
    auto issue=[&](int c){
        int buf=c&3, hc=hbase+c*CH;
        uint32_t* vb=VB(buf); uint32_t* ub=UB(buf); float* bb=BB(buf);
        { int row=tid>>3, qq=tid&7;
          cpa(&vb[row*40+qq*4], v1e+(size_t)row*H_+hc+qq*4); }
        { int row=tid>>4, qq=tid&15;
          cpa(&ub[row*72+qq*4], u2e+(size_t)(hc/2+row)*R_+qq*4); }
        if (tid<8) cpa(&bb[tid*4], b1e+hc+tid*4);
    };
    issue(0); CPC; issue(1); CPC; issue(2); CPC;   // weights (prert data) pre-wait
    GDC_WAIT();                                      // t1 outputs
    {
        const float4* pa=(const float4*)(g_t1p) + (size_t)p0*16;
        const float4* pb=pa + (size_t)P_PAD*16;
        const float4* pc=pb + (size_t)P_PAD*16;
        const float4* pd=pc + (size_t)P_PAD*16;
#pragma unroll
        for (int j=0;j<8;j++){
            int i=tid+j*256, row=i>>4, qq=i&15;
            float4 a=pa[i], b=pb[i], c=pc[i], d=pd[i];
            *(__half2*)(t1s+row*72+qq*4)   = __floats2half2_rn(a.x+b.x+c.x+d.x, a.y+b.y+c.y+d.y);
            *(__half2*)(t1s+row*72+qq*4+2) = __floats2half2_rn(a.z+b.z+c.z+d.z, a.w+b.w+c.w+d.w);
        }
    }
    CPW2;
    __syncthreads();
    uint32_t t1s_u = s2u(t1s), hs_u = s2u(hs);
    uint32_t fa1[4][2][4];
#pragma unroll
    for (int kk=0;kk<4;kk++)
#pragma unroll
        for (int mi=0;mi<2;mi++)
            ldmA(fa1[kk][mi], t1s_u + (uint32_t)(((wm*32+mi*16+lr)*72 + kk*16 + lc)*2));
    float acc2[2][4][4];
#pragma unroll
    for (int a=0;a<2;a++)
#pragma unroll
        for (int b=0;b<4;b++)
#pragma unroll
            for (int qq=0;qq<4;qq++) acc2[a][b][qq]=0.f;

    auto doG1=[&](int c){
        const uint32_t* vb=VB(c&3); const float* bb=BB(c&3);
        __half* hdst = hs + (size_t)(c&1)*128*40;
        float acc1[2][2][4];
#pragma unroll
        for (int a=0;a<2;a++)
#pragma unroll
            for (int b=0;b<2;b++)
#pragma unroll
                for (int qq=0;qq<4;qq++) acc1[a][b][qq]=0.f;
#pragma unroll
        for (int kk=0;kk<4;kk++){
#pragma unroll
            for (int ni=0;ni<2;ni++){
                int n=wn*16+ni*8+grp;
                uint32_t b0=vb[(8*kk+tig)*40+n], b1r=vb[(8*kk+tig+4)*40+n];
#pragma unroll
                for (int mi=0;mi<2;mi++)
                    mma16(acc1[mi][ni],fa1[kk][mi][0],fa1[kk][mi][1],fa1[kk][mi][2],fa1[kk][mi][3],b0,b1r);
            }
        }
#pragma unroll
        for (int mi=0;mi<2;mi++)
#pragma unroll
            for (int ni=0;ni<2;ni++){
                int r0=wm*32+mi*16+grp, c0=wn*16+ni*8+2*tig;
                float bb0=bb[c0], bb1=bb[c0+1];
                *(__half2*)(hdst+r0*40+c0) =
                    __floats2half2_rn(fmaxf(acc1[mi][ni][0]+bb0,0.f), fmaxf(acc1[mi][ni][1]+bb1,0.f));
                *(__half2*)(hdst+(r0+8)*40+c0) =
                    __floats2half2_rn(fmaxf(acc1[mi][ni][2]+bb0,0.f), fmaxf(acc1[mi][ni][3]+bb1,0.f));
            }
    };
    auto doG2=[&](int c){
        const uint32_t* ub=UB(c&3);
        uint32_t hsrc = hs_u + (uint32_t)((c&1)*128*40*2);
#pragma unroll
        for (int kk=0;kk<2;kk++){
            uint32_t fa[2][4];
#pragma unroll
            for (int mi=0;mi<2;mi++)
                ldmA(fa[mi], hsrc + (uint32_t)(((wm*32+mi*16+lr)*40 + kk*16 + lc)*2));
#pragma unroll
            for (int ni=0;ni<4;ni++){
                int n=wn*32+ni*8+grp;
                uint32_t b0=ub[(8*kk+tig)*72+n], b1r=ub[(8*kk+tig+4)*72+n];
#pragma unroll
                for (int mi=0;mi<2;mi++)
                    mma16(acc2[mi][ni],fa[mi][0],fa[mi][1],fa[mi][2],fa[mi][3],b0,b1r);
            }
        }
    };

    doG1(0);
    for (int c=1;c<NCM;c++){
        if (c+1<NCM) { CPW1; } else { CPW0; }
        __syncthreads();
        if (c+2<NCM) { issue(c+2); CPC; }
        doG2(c-1);
        doG1(c);
    }
    __syncthreads();
    doG2(NCM-1);

    float* dst=g_t2+(size_t)q*P_PAD*R_;
#pragma unroll
    for (int mi=0;mi<2;mi++)
#pragma unroll
        for (int ni=0;ni<4;ni++){
            int r0=wm*32+mi*16+grp, c0=wn*32+ni*8+2*tig;
            *(float2*)(dst+(size_t)(p0+r0)*R_+c0)   = make_float2(acc2[mi][ni][0],acc2[mi][ni][1]);
            *(float2*)(dst+(size_t)(p0+r0+8)*R_+c0) = make_float2(acc2[mi][ni][2],acc2[mi][ni][3]);
        }
}

// ---------------- y = w * (t2 @ v2 + b2) (fp16, half output) -----------------
#define Y_SMEM (64*72*2 + 2*32*136*4 + 2*128*4 + 64*4)
__global__ __launch_bounds__(256) void k_y(const float* __restrict__ b2) {
    GDC_LAUNCH();
    int e=g_te64[blockIdx.x];         // sa output: complete
    if (e<0) { GDC_WAIT(); return; }
    int p0=blockIdx.x*64;
    extern __shared__ __align__(16) char smraw[];
    __half*   t2s=(__half*)smraw;
    uint32_t* v2s=(uint32_t*)(smraw+64*72*2);
    float*    b2s=(float*)(smraw+64*72*2+2*32*136*4);
    float*    ws =b2s+2*128;
    int tid=threadIdx.x, warp=tid>>5, lane=tid&31;
    int grp=lane>>2, tig=lane&3, wm=warp>>2, wn=warp&3;
    int lr=lane&15, lc=(lane>>4)*8;
    const uint32_t* v2e=g_v2p+(size_t)e*(R_/2)*D_;
    const float* b2e=b2+(size_t)e*D_;
    const int NC=D_/128;
    auto issue=[&](int c){
        int buf=c&1, dc=c*128;
        uint32_t* vb=v2s+buf*32*136; float* bb=b2s+buf*128;
#pragma unroll
        for (int j=0;j<4;j++){int idx=tid+j*256, row=idx>>5, qq=idx&31;
            cpa(&vb[row*136+qq*4], v2e+(size_t)row*D_+dc+qq*4);}
        if (tid<32) cpa(&bb[tid*4], b2e+dc+tid*4);
    };
    if (tid<64) ws[tid]=g_pw[p0+tid];   // sa output: complete
    issue(0); CPC;                      // prert weights: complete
    GDC_WAIT();                         // mid outputs
    const float4* q0=(const float4*)g_t2 + (size_t)p0*16;
    const float4* q1=q0 + (size_t)P_PAD*16;
    const float4* q2=q1 + (size_t)P_PAD*16;
    const float4* q3=q2 + (size_t)P_PAD*16;
#pragma unroll
    for (int j=0;j<4;j++){
        int i=tid+j*256, row=i>>4, cq=i&15;
        float4 a=q0[i], b=q1[i], c=q2[i], d=q3[i];
        *(__half2*)(t2s+row*72+cq*4)   = __floats2half2_rn(a.x+b.x+c.x+d.x, a.y+b.y+c.y+d.y);
        *(__half2*)(t2s+row*72+cq*4+2) = __floats2half2_rn(a.z+b.z+c.z+d.z, a.w+b.w+c.w+d.w);
    }
    uint32_t t2s_u = s2u(t2s);
    for (int c=0;c<NC;c++){
        if (c>0) __syncthreads();
        if (c+1<NC){ issue(c+1); CPC; CPW1; } else { CPW0; }
        __syncthreads();
        int buf=c&1, dc=c*128;
        const uint32_t* vb=v2s+buf*32*136; const float* bb=b2s+buf*128;
        float acc[2][4][4];
#pragma unroll
        for (int a=0;a<2;a++)
#pragma unroll
            for (int b=0;b<4;b++)
#pragma unroll
                for (int qq=0;qq<4;qq++) acc[a][b][qq]=0.f;
#pragma unroll
        for (int kk=0;kk<4;kk++){
            uint32_t fa[2][4];
#pragma unroll
            for (int mi=0;mi<2;mi++)
                ldmA(fa[mi], t2s_u + (uint32_t)(((wm*32+mi*16+lr)*72 + kk*16 + lc)*2));
#pragma unroll
            for (int ni=0;ni<4;ni++){
                int n=wn*32+ni*8+grp;
                uint32_t b0=vb[(8*kk+tig)*136+n], b1r=vb[(8*kk+tig+4)*136+n];
#pragma unroll
                for (int mi=0;mi<2;mi++)
                    mma16(acc[mi][ni],fa[mi][0],fa[mi][1],fa[mi][2],fa[mi][3],b0,b1r);
            }
        }
#pragma unroll
        for (int mi=0;mi<2;mi++)
#pragma unroll
            for (int ni=0;ni<4;ni++){
                int r0=wm*32+mi*16+grp, c0=wn*32+ni*8+2*tig;
                float w0v=ws[r0], w1v=ws[r0+8], bb0=bb[c0], bb1=bb[c0+1];
                *(__half2*)(g_py+(size_t)(p0+r0)*D_+dc+c0)   =
                    __floats2half2_rn(w0v*(acc[mi][ni][0]+bb0), w0v*(acc[mi][ni][1]+bb1));
                *(__half2*)(g_py+(size_t)(p0+r0+8)*D_+dc+c0) =
                    __floats2half2_rn(w1v*(acc[mi][ni][2]+bb0), w1v*(acc[mi][ni][3]+bb1));
            }
    }
}

__global__ void k_combine(float* __restrict__ out) {
    int n=blockIdx.x;
    int pa=g_entry[2*n], pb=g_entry[2*n+1];   // sa output: complete
    GDC_WAIT();                                // y outputs
    const uint4* a=(const uint4*)(g_py+(size_t)pa*D_);
    const uint4* b=(const uint4*)(g_py+(size_t)pb*D_);
    float4* o=(float4*)(out+(size_t)n*D_);
    for (int j=threadIdx.x;j<D_/8;j+=blockDim.x){
        uint4 va=a[j], vb=b[j];
        float2 a0=__half22float2(*(__half2*)&va.x), b0=__half22float2(*(__half2*)&vb.x);
        float2 a1=__half22float2(*(__half2*)&va.y), b1=__half22float2(*(__half2*)&vb.y);
        float2 a2=__half22float2(*(__half2*)&va.z), b2=__half22float2(*(__half2*)&vb.z);
        float2 a3=__half22float2(*(__half2*)&va.w), b3=__half22float2(*(__half2*)&vb.w);
        o[2*j]   = make_float4(a0.x+b0.x, a0.y+b0.y, a1.x+b1.x, a1.y+b1.y);
        o[2*j+1] = make_float4(a2.x+b2.x, a2.y+b2.y, a3.x+b3.x, a3.y+b3.y);
    }
}

// ------------------------------- launch --------------------------------------
template <class K, class... Args>
static void pdl_launch(K kern, dim3 g, dim3 b, size_t smem, Args... args) {
    cudaLaunchConfig_t cfg = {};
    cfg.gridDim = g; cfg.blockDim = b; cfg.dynamicSmemBytes = smem; cfg.stream = 0;
    cudaLaunchAttribute at;
    at.id = cudaLaunchAttributeProgrammaticStreamSerialization;
    at.val.programmaticStreamSerializationAllowed = 1;
    cfg.attrs = &at; cfg.numAttrs = 1;
    cudaLaunchKernelEx(&cfg, kern, args...);
}

extern "C" void kernel_launch(void* const* d_in, const int* in_sizes, int n_in,
                              void* d_out, int out_size) {
    const float* x  = (const float*)d_in[0];
    const float* u1 = (const float*)d_in[1];
    const float* v1 = (const float*)d_in[2];
    const float* b1 = (const float*)d_in[3];
    const float* u2 = (const float*)d_in[4];
    const float* v2 = (const float*)d_in[5];
    const float* b2 = (const float*)d_in[6];
    const float* gw = (const float*)d_in[7];
    const float* gb = (const float*)d_in[8];
    float* out = (float*)d_out;

    static bool attr_done = false;
    if (!attr_done) {
        cudaFuncSetAttribute(k_t1,  cudaFuncAttributeMaxDynamicSharedMemorySize, T1_SMEM);
        cudaFuncSetAttribute(k_mid, cudaFuncAttributeMaxDynamicSharedMemorySize, MID_SMEM);
        cudaFuncSetAttribute(k_y,   cudaFuncAttributeMaxDynamicSharedMemorySize, Y_SMEM);
        attr_done = true;
    }

    k_prert<<<1536, 256>>>(x, gw, gb, u1, v1, u2, v2);
    pdl_launch(k_sa,      dim3(1),      dim3(1024), 0);
    pdl_launch(k_t1,      dim3(T64*4),  dim3(256),  (size_t)T1_SMEM);
    pdl_launch(k_mid,     dim3(T128*4), dim3(256),  (size_t)MID_SMEM, b1);
    pdl_launch(k_y,       dim3(T64),    dim3(256),  (size_t)Y_SMEM,   b2);
    pdl_launch(k_combine, dim3(N_),     dim3(256),  (size_t)0,        out);
}

// round 16
// speedup vs baseline: 1.2864x; 1.2864x over previous
#include <cuda_runtime.h>
#include <cuda_fp16.h>
#include <cstdint>
#include <math.h>

#define E_ 8
#define D_ 2048
#define H_ 8192
#define R_ 64
#define N_ 4096
#define T64 144
#define T128 72
#define P_PAD (T128*128)

__device__ __align__(16) __half    g_xh [(size_t)N_*D_];
__device__ __align__(16) uint32_t  g_u1p[(size_t)E_*(D_/2)*R_];   // [E][D/2][R]
__device__ __align__(16) uint32_t  g_v1p[(size_t)E_*(R_/2)*H_];   // [E][R/2][H]
__device__ __align__(16) uint32_t  g_u2p[(size_t)E_*(H_/2)*R_];   // [E][H/2][R]
__device__ __align__(16) uint32_t  g_v2p[(size_t)E_*(R_/2)*D_];   // [E][R/2][D]
__device__ __align__(16) float     g_t1p[(size_t)4*P_PAD*R_];     // 4 K-quarter partials
__device__ __align__(16) __half    g_t2h[(size_t)4*P_PAD*R_];     // 4 H-quarter partials (half)
__device__ __align__(16) __half    g_py [(size_t)P_PAD*D_];
__device__ int   g_ptok[P_PAD];
__device__ float g_pw  [P_PAD];
__device__ int   g_entry[2*N_];
__device__ int   g_re[2*N_];
__device__ float g_rw[2*N_];
__device__ int   g_cnt[E_];                 // static-init 0; reset each run by k_sa
__device__ int   g_te64[T64];
__device__ int   g_te128[T128];

// ------------------------------- helpers ------------------------------------
__device__ __forceinline__ void mma16(float c[4], uint32_t a0, uint32_t a1,
                                      uint32_t a2, uint32_t a3,
                                      uint32_t b0, uint32_t b1) {
    asm volatile("mma.sync.aligned.m16n8k16.row.col.f32.f16.f16.f32 "
        "{%0,%1,%2,%3}, {%4,%5,%6,%7}, {%8,%9}, {%0,%1,%2,%3};"
        : "+f"(c[0]), "+f"(c[1]), "+f"(c[2]), "+f"(c[3])
        : "r"(a0), "r"(a1), "r"(a2), "r"(a3), "r"(b0), "r"(b1));
}
__device__ __forceinline__ void ldmA(uint32_t a[4], uint32_t addr) {
    asm volatile("ldmatrix.sync.aligned.m8n8.x4.shared.b16 {%0,%1,%2,%3}, [%4];"
        : "=r"(a[0]), "=r"(a[1]), "=r"(a[2]), "=r"(a[3]) : "r"(addr));
}
__device__ __forceinline__ uint32_t s2u(const void* p) {
    return (uint32_t)__cvta_generic_to_shared(p);
}
__device__ __forceinline__ void cpa(void* s, const void* g) {
    uint32_t sa=(uint32_t)__cvta_generic_to_shared(s);
    asm volatile("cp.async.cg.shared.global [%0], [%1], 16;" :: "r"(sa), "l"(g));
}
#define CPC  asm volatile("cp.async.commit_group;" ::: "memory")
#define CPW0 asm volatile("cp.async.wait_group 0;" ::: "memory")
#define CPW1 asm volatile("cp.async.wait_group 1;" ::: "memory")
#define CPW2 asm volatile("cp.async.wait_group 2;" ::: "memory")

// merged: blocks [0,512) = route + x->half ; blocks [512,1536) = weight packing
__global__ __launch_bounds__(256) void k_prert(
        const float* __restrict__ x, const float* __restrict__ gw,
        const float* __restrict__ gb,
        const float* __restrict__ u1, const float* __restrict__ v1,
        const float* __restrict__ u2, const float* __restrict__ v2) {
    if (blockIdx.x < 512) {
        int warp=threadIdx.x>>5, lane=threadIdx.x&31;
        int n = blockIdx.x*8 + warp;
        const float4* xr = (const float4*)(x + (size_t)n*D_);
        float4 xv[16];
#pragma unroll
        for (int i=0;i<16;i++) xv[i]=xr[lane+i*32];
#pragma unroll
        for (int i=0;i<16;i++){
            __half* dst = g_xh + (size_t)n*D_ + (size_t)(lane+i*32)*4;
            *(__half2*)dst     = __floats2half2_rn(xv[i].x, xv[i].y);
            *(__half2*)(dst+2) = __floats2half2_rn(xv[i].z, xv[i].w);
        }
        float lg[8];
#pragma unroll
        for (int e=0;e<8;e++){
            const float4* gr=(const float4*)(gw+(size_t)e*D_);
            float s=0.f;
#pragma unroll
            for (int i=0;i<16;i++){float4 g=gr[lane+i*32];
                s+=xv[i].x*g.x+xv[i].y*g.y+xv[i].z*g.z+xv[i].w*g.w;}
#pragma unroll
            for (int o=16;o>0;o>>=1) s+=__shfl_xor_sync(0xffffffffu,s,o);
            lg[e]=s+gb[e];
        }
        if (lane==0){
            int e0=0; float m0=lg[0];
#pragma unroll
            for (int e=1;e<8;e++) if (lg[e]>m0){m0=lg[e];e0=e;}
            int e1=-1; float m1=-3.4e38f;
#pragma unroll
            for (int e=0;e<8;e++) if (e!=e0 && lg[e]>m1){m1=lg[e];e1=e;}
            float w0=1.f/(1.f+expf(m1-m0));
            g_re[2*n]=e0; g_rw[2*n]=w0; g_re[2*n+1]=e1; g_rw[2*n+1]=1.f-w0;
            atomicAdd(&g_cnt[e0],1); atomicAdd(&g_cnt[e1],1);
        }
        return;
    }
    int tid = (blockIdx.x-512)*blockDim.x + threadIdx.x, st = 1024*blockDim.x;
    for (int i=tid;i<P_PAD;i+=st){ g_ptok[i]=0; g_pw[i]=0.f; }
    for (int i=tid;i<E_*(D_/2)*R_;i+=st){
        int e=i/((D_/2)*R_), rem=i%((D_/2)*R_), kk=rem/R_, r=rem%R_;
        const float* s=u1+(size_t)e*D_*R_+(size_t)(2*kk)*R_+r;
        ((__half2*)g_u1p)[i]=__floats2half2_rn(s[0], s[R_]);
    }
    for (int i=tid;i<E_*(R_/2)*H_;i+=st){
        int e=i/((R_/2)*H_), rem=i%((R_/2)*H_), kk=rem/H_, h=rem%H_;
        const float* s=v1+(size_t)e*R_*H_+(size_t)(2*kk)*H_+h;
        ((__half2*)g_v1p)[i]=__floats2half2_rn(s[0], s[H_]);
    }
    for (int i=tid;i<E_*(H_/2)*R_;i+=st){
        int e=i/((H_/2)*R_), rem=i%((H_/2)*R_), hh=rem/R_, r=rem%R_;
        const float* s=u2+(size_t)e*H_*R_+(size_t)(2*hh)*R_+r;
        ((__half2*)g_u2p)[i]=__floats2half2_rn(s[0], s[R_]);
    }
    for (int i=tid;i<E_*(R_/2)*D_;i+=st){
        int e=i/((R_/2)*D_), rem=i%((R_/2)*D_), kk=rem/D_, d=rem%D_;
        const float* s=v2+(size_t)e*R_*D_+(size_t)(2*kk)*D_+d;
        ((__half2*)g_v2p)[i]=__floats2half2_rn(s[0], s[D_]);
    }
}

// fused scan + assign : ONE block, 1024 threads, smem counters.
__global__ __launch_bounds__(1024) void k_sa() {
    __shared__ int pre[E_+1];
    __shared__ int cur[E_];
    int tid=threadIdx.x, lane=tid&31;
    if (tid==0){
        int run=0;
        for (int e=0;e<E_;e++){ pre[e]=run; cur[e]=run;
            run += ((g_cnt[e]+127)>>7)<<7;
            g_cnt[e]=0; }
        pre[E_]=run;
    }
    __syncthreads();
    if (tid<T64){
        int r=tid*64, e=-1;
#pragma unroll
        for (int i=0;i<E_;i++) if (r>=pre[i] && r<pre[i+1]) e=i;
        g_te64[tid]=e;
    }
    if (tid<T128){
        int r=tid*128, e=-1;
#pragma unroll
        for (int i=0;i<E_;i++) if (r>=pre[i] && r<pre[i+1]) e=i;
        g_te128[tid]=e;
    }
    for (int n=tid;n<N_;n+=1024){
#pragma unroll
        for (int k=0;k<2;k++){
            int e=g_re[2*n+k];
            unsigned mask=__match_any_sync(0xffffffffu, e);
            int leader=__ffs(mask)-1;
            int rank=__popc(mask & ((1u<<lane)-1u));
            int base=0;
            if (lane==leader) base=atomicAdd(&cur[e], __popc(mask));
            base=__shfl_sync(0xffffffffu, base, leader);
            int pos=base+rank;
            g_ptok[pos]=n; g_pw[pos]=g_rw[2*n+k]; g_entry[2*n+k]=pos;
        }
    }
}

// ----- t1 partial = x @ u1 over one K-quarter (fp16, fp32 partial out) -------
#define T1_SMEM (256 + 2*64*72*2 + 2*32*72*4)
__global__ __launch_bounds__(256,3) void k_t1() {
    int tile=blockIdx.x>>2, kq=blockIdx.x&3;
    int e=g_te64[tile]; if (e<0) return;
    int p0=tile*64, kbase=kq*(D_/4);
    extern __shared__ __align__(16) char smraw[];
    int*      tok=(int*)smraw;
    __half*   as=(__half*)(smraw+256);
    uint32_t* bs=(uint32_t*)(smraw+256+2*64*72*2);
    int tid=threadIdx.x, warp=tid>>5, lane=tid&31;
    int grp=lane>>2, tig=lane&3, wm=warp>>2, wn=warp&3;
    int lr=lane&15, lc=(lane>>4)*8;
    if (tid<64) tok[tid]=g_ptok[p0+tid];
    __syncthreads();
    const uint32_t* u1e = g_u1p + (size_t)e*(D_/2)*R_;
    const int NC=(D_/4)/64;
    uint32_t as_u = s2u(as);
    auto issue=[&](int c){
        int buf=c&1, k0=kbase+c*64;
        __half* ab=as+buf*64*72; uint32_t* bb=bs+buf*32*72;
#pragma unroll
        for (int j=0;j<2;j++){int idx=tid+j*256, row=idx>>3, q=idx&7;
            cpa(&ab[row*72+q*8], g_xh+(size_t)tok[row]*D_+k0+q*8);}
#pragma unroll
        for (int j=0;j<2;j++){int idx=tid+j*256, row=idx>>4, q=idx&15;
            cpa(&bb[row*72+q*4], u1e+(size_t)(k0/2+row)*R_+q*4);}
    };
    float acc[2][2][4];
#pragma unroll
    for (int a=0;a<2;a++)
#pragma unroll
        for (int b=0;b<2;b++)
#pragma unroll
            for (int q=0;q<4;q++) acc[a][b][q]=0.f;
    issue(0); CPC;
    for (int c=0;c<NC;c++){
        if (c>0) __syncthreads();
        if (c+1<NC){ issue(c+1); CPC; CPW1; } else { CPW0; }
        __syncthreads();
        int buf=c&1;
        uint32_t ab_u = as_u + (uint32_t)buf*64*72*2;
        const uint32_t* bb=bs+buf*32*72;
#pragma unroll
        for (int kk=0;kk<4;kk++){
            uint32_t fa[2][4];
#pragma unroll
            for (int mi=0;mi<2;mi++)
                ldmA(fa[mi], ab_u + (uint32_t)(((wm*32+mi*16+lr)*72 + kk*16 + lc)*2));
#pragma unroll
            for (int ni=0;ni<2;ni++){
                int n=wn*16+ni*8+grp;
                uint32_t b0=bb[(8*kk+tig)*72+n], b1=bb[(8*kk+tig+4)*72+n];
#pragma unroll
                for (int mi=0;mi<2;mi++)
                    mma16(acc[mi][ni],fa[mi][0],fa[mi][1],fa[mi][2],fa[mi][3],b0,b1);
            }
        }
    }
    float* dst = g_t1p + (size_t)kq*P_PAD*R_;
#pragma unroll
    for (int mi=0;mi<2;mi++)
#pragma unroll
        for (int ni=0;ni<2;ni++){
            int r0=wm*32+mi*16+grp, c0=wn*16+ni*8+2*tig;
            *(float2*)(dst+(size_t)(p0+r0)*R_+c0)   = make_float2(acc[mi][ni][0],acc[mi][ni][1]);
            *(float2*)(dst+(size_t)(p0+r0+8)*R_+c0) = make_float2(acc[mi][ni][2],acc[mi][ni][3]);
        }
}

// -------- mid: pipelined t2_q = relu(t1@v1+b1)@u2 over one H-quarter ---------
// 32-wide chunks, 4 weight buffers, 2 h buffers, ONE sync per chunk.
#define CH 32
#define NCM ((H_/4)/CH)
#define OFF_T1S 0
#define OFF_HS  (128*72*2)
#define OFF_W   (OFF_HS + 2*128*40*2)
#define WBUF    (32*40*4 + 16*72*4 + 32*4)
#define MID_SMEM (OFF_W + 4*WBUF)
__global__ __launch_bounds__(256,2) void k_mid(const float* __restrict__ b1) {
    int tile=blockIdx.x>>2, q=blockIdx.x&3;
    int e=g_te128[tile]; if (e<0) return;
    int p0=tile*128, hbase=q*(H_/4);
    extern __shared__ __align__(16) char smraw[];
    __half* t1s=(__half*)(smraw+OFF_T1S);       // 128 x 72
    __half* hs =(__half*)(smraw+OFF_HS);        // 2 x 128 x 40
    char*   wb =(char*)(smraw+OFF_W);           // 4 x (vb[32][40] + ub[16][72] + b1[32])
    int tid=threadIdx.x, warp=tid>>5, lane=tid&31;
    int grp=lane>>2, tig=lane&3, wm=warp&3, wn=warp>>2;   // wn in {0,1}
    int lr=lane&15, lc=(lane>>4)*8;
    const uint32_t* v1e = g_v1p + (size_t)e*(R_/2)*H_;
    const uint32_t* u2e = g_u2p + (size_t)e*(H_/2)*R_;
    const float*    b1e = b1 + (size_t)e*H_;
    auto VB=[&](int buf)->uint32_t* { return (uint32_t*)(wb + buf*WBUF); };
    auto UB=[&](int buf)->uint32_t* { return (uint32_t*)(wb + buf*WBUF + 32*40*4); };
    auto BB=[&](int buf)->float*    { return (float*)(wb + buf*WBUF + 32*40*4 + 16*72*4); };
    auto issue=[&](int c){
        int buf=c&3, hc=hbase+c*CH;
        uint32_t* vb=VB(buf); uint32_t* ub=UB(buf); float* bb=BB(buf);
        { int row=tid>>3, qq=tid&7;
          cpa(&vb[row*40+qq*4], v1e+(size_t)row*H_+hc+qq*4); }
        { int row=tid>>4, qq=tid&15;
          cpa(&ub[row*72+qq*4], u2e+(size_t)(hc/2+row)*R_+qq*4); }
        if (tid<8) cpa(&bb[tid*4], b1e+hc+tid*4);
    };
    issue(0); CPC; issue(1); CPC; issue(2); CPC;
    // t1s = sum of 4 fp32 K-quarter partials -> half
    {
        const float4* pa=(const float4*)(g_t1p) + (size_t)p0*16;
        const float4* pb=pa + (size_t)P_PAD*16;
        const float4* pc=pb + (size_t)P_PAD*16;
        const float4* pd=pc + (size_t)P_PAD*16;
#pragma unroll
        for (int j=0;j<8;j++){
            int i=tid+j*256, row=i>>4, qq=i&15;
            float4 a=pa[i], b=pb[i], c=pc[i], d=pd[i];
            *(__half2*)(t1s+row*72+qq*4)   = __floats2half2_rn(a.x+b.x+c.x+d.x, a.y+b.y+c.y+d.y);
            *(__half2*)(t1s+row*72+qq*4+2) = __floats2half2_rn(a.z+b.z+c.z+d.z, a.w+b.w+c.w+d.w);
        }
    }
    CPW2;
    __syncthreads();
    uint32_t t1s_u = s2u(t1s), hs_u = s2u(hs);
    uint32_t fa1[4][2][4];
#pragma unroll
    for (int kk=0;kk<4;kk++)
#pragma unroll
        for (int mi=0;mi<2;mi++)
            ldmA(fa1[kk][mi], t1s_u + (uint32_t)(((wm*32+mi*16+lr)*72 + kk*16 + lc)*2));
    float acc2[2][4][4];
#pragma unroll
    for (int a=0;a<2;a++)
#pragma unroll
        for (int b=0;b<4;b++)
#pragma unroll
            for (int qq=0;qq<4;qq++) acc2[a][b][qq]=0.f;

    auto doG1=[&](int c){
        const uint32_t* vb=VB(c&3); const float* bb=BB(c&3);
        __half* hdst = hs + (size_t)(c&1)*128*40;
        float acc1[2][2][4];
#pragma unroll
        for (int a=0;a<2;a++)
#pragma unroll
            for (int b=0;b<2;b++)
#pragma unroll
                for (int qq=0;qq<4;qq++) acc1[a][b][qq]=0.f;
#pragma unroll
        for (int kk=0;kk<4;kk++){
#pragma unroll
            for (int ni=0;ni<2;ni++){
                int n=wn*16+ni*8+grp;
                uint32_t b0=vb[(8*kk+tig)*40+n], b1r=vb[(8*kk+tig+4)*40+n];
#pragma unroll
                for (int mi=0;mi<2;mi++)
                    mma16(acc1[mi][ni],fa1[kk][mi][0],fa1[kk][mi][1],fa1[kk][mi][2],fa1[kk][mi][3],b0,b1r);
            }
        }
#pragma unroll
        for (int mi=0;mi<2;mi++)
#pragma unroll
            for (int ni=0;ni<2;ni++){
                int r0=wm*32+mi*16+grp, c0=wn*16+ni*8+2*tig;
                float bb0=bb[c0], bb1=bb[c0+1];
                *(__half2*)(hdst+r0*40+c0) =
                    __floats2half2_rn(fmaxf(acc1[mi][ni][0]+bb0,0.f), fmaxf(acc1[mi][ni][1]+bb1,0.f));
                *(__half2*)(hdst+(r0+8)*40+c0) =
                    __floats2half2_rn(fmaxf(acc1[mi][ni][2]+bb0,0.f), fmaxf(acc1[mi][ni][3]+bb1,0.f));
            }
    };
    auto doG2=[&](int c){
        const uint32_t* ub=UB(c&3);
        uint32_t hsrc = hs_u + (uint32_t)((c&1)*128*40*2);
#pragma unroll
        for (int kk=0;kk<2;kk++){
            uint32_t fa[2][4];
#pragma unroll
            for (int mi=0;mi<2;mi++)
                ldmA(fa[mi], hsrc + (uint32_t)(((wm*32+mi*16+lr)*40 + kk*16 + lc)*2));
#pragma unroll
            for (int ni=0;ni<4;ni++){
                int n=wn*32+ni*8+grp;
                uint32_t b0=ub[(8*kk+tig)*72+n], b1r=ub[(8*kk+tig+4)*72+n];
#pragma unroll
                for (int mi=0;mi<2;mi++)
                    mma16(acc2[mi][ni],fa[mi][0],fa[mi][1],fa[mi][2],fa[mi][3],b0,b1r);
            }
        }
    };

    doG1(0);
    for (int c=1;c<NCM;c++){
        if (c+1<NCM) { CPW1; } else { CPW0; }
        __syncthreads();
        if (c+2<NCM) { issue(c+2); CPC; }
        doG2(c-1);
        doG1(c);
    }
    __syncthreads();
    doG2(NCM-1);

    __half* dst=g_t2h+(size_t)q*P_PAD*R_;
#pragma unroll
    for (int mi=0;mi<2;mi++)
#pragma unroll
        for (int ni=0;ni<4;ni++){
            int r0=wm*32+mi*16+grp, c0=wn*32+ni*8+2*tig;
            *(__half2*)(dst+(size_t)(p0+r0)*R_+c0)   = __floats2half2_rn(acc2[mi][ni][0],acc2[mi][ni][1]);
            *(__half2*)(dst+(size_t)(p0+r0+8)*R_+c0) = __floats2half2_rn(acc2[mi][ni][2],acc2[mi][ni][3]);
        }
}

// ---------------- y = w * (t2 @ v2 + b2) (fp16, half output) -----------------
#define Y_SMEM (64*72*2 + 2*32*136*4 + 2*128*4 + 64*4)
__global__ __launch_bounds__(256) void k_y(const float* __restrict__ b2) {
    int e=g_te64[blockIdx.x]; if (e<0) return;
    int p0=blockIdx.x*64;
    extern __shared__ __align__(16) char smraw[];
    __half*   t2s=(__half*)smraw;
    uint32_t* v2s=(uint32_t*)(smraw+64*72*2);
    float*    b2s=(float*)(smraw+64*72*2+2*32*136*4);
    float*    ws =b2s+2*128;
    int tid=threadIdx.x, warp=tid>>5, lane=tid&31;
    int grp=lane>>2, tig=lane&3, wm=warp>>2, wn=warp&3;
    int lr=lane&15, lc=(lane>>4)*8;
    const uint32_t* v2e=g_v2p+(size_t)e*(R_/2)*D_;
    const float* b2e=b2+(size_t)e*D_;
    const int NC=D_/128;
    auto issue=[&](int c){
        int buf=c&1, dc=c*128;
        uint32_t* vb=v2s+buf*32*136; float* bb=b2s+buf*128;
#pragma unroll
        for (int j=0;j<4;j++){int idx=tid+j*256, row=idx>>5, qq=idx&31;
            cpa(&vb[row*136+qq*4], v2e+(size_t)row*D_+dc+qq*4);}
        if (tid<32) cpa(&bb[tid*4], b2e+dc+tid*4);
    };
    if (tid<64) ws[tid]=g_pw[p0+tid];
    // t2s = half( sum of 4 half H-quarter partials, fp32 accum, fixed order )
    const uint2* q0=(const uint2*)g_t2h + (size_t)p0*16;
    const uint2* q1=q0 + (size_t)P_PAD*16;
    const uint2* q2=q1 + (size_t)P_PAD*16;
    const uint2* q3=q2 + (size_t)P_PAD*16;
#pragma unroll
    for (int j=0;j<4;j++){
        int i=tid+j*256, row=i>>4, cq=i&15;
        uint2 a=q0[i], b=q1[i], c=q2[i], d=q3[i];
        float2 a0=__half22float2(*(__half2*)&a.x), a1=__half22float2(*(__half2*)&a.y);
        float2 b0=__half22float2(*(__half2*)&b.x), b1=__half22float2(*(__half2*)&b.y);
        float2 c0=__half22float2(*(__half2*)&c.x), c1=__half22float2(*(__half2*)&c.y);
        float2 d0=__half22float2(*(__half2*)&d.x), d1=__half22float2(*(__half2*)&d.y);
        *(__half2*)(t2s+row*72+cq*4)   = __floats2half2_rn(a0.x+b0.x+c0.x+d0.x, a0.y+b0.y+c0.y+d0.y);
        *(__half2*)(t2s+row*72+cq*4+2) = __floats2half2_rn(a1.x+b1.x+c1.x+d1.x, a1.y+b1.y+c1.y+d1.y);
    }
    issue(0); CPC;
    uint32_t t2s_u = s2u(t2s);
    for (int c=0;c<NC;c++){
        if (c>0) __syncthreads();
        if (c+1<NC){ issue(c+1); CPC; CPW1; } else { CPW0; }
        __syncthreads();
        int buf=c&1, dc=c*128;
        const uint32_t* vb=v2s+buf*32*136; const float* bb=b2s+buf*128;
        float acc[2][4][4];
#pragma unroll
        for (int a=0;a<2;a++)
#pragma unroll
            for (int b=0;b<4;b++)
#pragma unroll
                for (int qq=0;qq<4;qq++) acc[a][b][qq]=0.f;
#pragma unroll
        for (int kk=0;kk<4;kk++){
            uint32_t fa[2][4];
#pragma unroll
            for (int mi=0;mi<2;mi++)
                ldmA(fa[mi], t2s_u + (uint32_t)(((wm*32+mi*16+lr)*72 + kk*16 + lc)*2));
#pragma unroll
            for (int ni=0;ni<4;ni++){
                int n=wn*32+ni*8+grp;
                uint32_t b0=vb[(8*kk+tig)*136+n], b1r=vb[(8*kk+tig+4)*136+n];
#pragma unroll
                for (int mi=0;mi<2;mi++)
                    mma16(acc[mi][ni],fa[mi][0],fa[mi][1],fa[mi][2],fa[mi][3],b0,b1r);
            }
        }
#pragma unroll
        for (int mi=0;mi<2;mi++)
#pragma unroll
            for (int ni=0;ni<4;ni++){
                int r0=wm*32+mi*16+grp, c0=wn*32+ni*8+2*tig;
                float w0v=ws[r0], w1v=ws[r0+8], bb0=bb[c0], bb1=bb[c0+1];
                *(__half2*)(g_py+(size_t)(p0+r0)*D_+dc+c0)   =
                    __floats2half2_rn(w0v*(acc[mi][ni][0]+bb0), w0v*(acc[mi][ni][1]+bb1));
                *(__half2*)(g_py+(size_t)(p0+r0+8)*D_+dc+c0) =
                    __floats2half2_rn(w1v*(acc[mi][ni][2]+bb0), w1v*(acc[mi][ni][3]+bb1));
            }
    }
}

__global__ void k_combine(float* __restrict__ out) {
    int n=blockIdx.x;
    int pa=g_entry[2*n], pb=g_entry[2*n+1];
    const uint4* a=(const uint4*)(g_py+(size_t)pa*D_);
    const uint4* b=(const uint4*)(g_py+(size_t)pb*D_);
    float4* o=(float4*)(out+(size_t)n*D_);
    for (int j=threadIdx.x;j<D_/8;j+=blockDim.x){
        uint4 va=a[j], vb=b[j];
        float2 a0=__half22float2(*(__half2*)&va.x), b0=__half22float2(*(__half2*)&vb.x);
        float2 a1=__half22float2(*(__half2*)&va.y), b1=__half22float2(*(__half2*)&vb.y);
        float2 a2=__half22float2(*(__half2*)&va.z), b2=__half22float2(*(__half2*)&vb.z);
        float2 a3=__half22float2(*(__half2*)&va.w), b3=__half22float2(*(__half2*)&vb.w);
        o[2*j]   = make_float4(a0.x+b0.x, a0.y+b0.y, a1.x+b1.x, a1.y+b1.y);
        o[2*j+1] = make_float4(a2.x+b2.x, a2.y+b2.y, a3.x+b3.x, a3.y+b3.y);
    }
}

extern "C" void kernel_launch(void* const* d_in, const int* in_sizes, int n_in,
                              void* d_out, int out_size) {
    const float* x  = (const float*)d_in[0];
    const float* u1 = (const float*)d_in[1];
    const float* v1 = (const float*)d_in[2];
    const float* b1 = (const float*)d_in[3];
    const float* u2 = (const float*)d_in[4];
    const float* v2 = (const float*)d_in[5];
    const float* b2 = (const float*)d_in[6];
    const float* gw = (const float*)d_in[7];
    const float* gb = (const float*)d_in[8];
    float* out = (float*)d_out;

    static bool attr_done = false;
    if (!attr_done) {
        cudaFuncSetAttribute(k_t1,  cudaFuncAttributeMaxDynamicSharedMemorySize, T1_SMEM);
        cudaFuncSetAttribute(k_mid, cudaFuncAttributeMaxDynamicSharedMemorySize, MID_SMEM);
        cudaFuncSetAttribute(k_y,   cudaFuncAttributeMaxDynamicSharedMemorySize, Y_SMEM);
        attr_done = true;
    }

    k_prert<<<1536, 256>>>(x, gw, gb, u1, v1, u2, v2);
    k_sa<<<1, 1024>>>();
    k_t1<<<T64*4, 256, T1_SMEM>>>();
    k_mid<<<T128*4, 256, MID_SMEM>>>(b1);
    k_y<<<T64, 256, Y_SMEM>>>(b2);
    k_combine<<<N_, 256>>>(out);
}